// round 1
// baseline (speedup 1.0000x reference)
#include <cuda_runtime.h>

// ----------------------------------------------------------------------------
// Tropical (max-plus) Vision Transformer, fp32.
// All tropical matmuls are NT GEMMs: C[m,n] = max_k (A[m,k] + B[n,k]).
// ----------------------------------------------------------------------------

#define NEG_INF (-3.0e38f)

#define BB     8
#define NPATCH 196
#define DD     128
#define DFF    256
#define PDIM   256
#define NPAD   224      // 196 padded to multiple of 32
#define MTOT   1568     // BB * NPATCH  (== 49*32, multiple of 32)
#define NCLS   1000

// scratch (static device arrays; zero-initialized once, pads never rewritten)
__device__ float g_patches[BB * NPATCH * PDIM];
__device__ float g_h   [MTOT * DD];
__device__ float g_xn  [MTOT * DD];
__device__ float g_q   [MTOT * DD];
__device__ float g_k   [MTOT * DD];
__device__ float g_vT  [BB * DD * NPAD];      // [b][d][j], j padded with 0
__device__ float g_s   [BB * NPATCH * NPAD];  // [b][i][j], j pad = -1e30
__device__ float g_a   [MTOT * DD];           // attn out / ff out
__device__ float g_h1  [MTOT * DFF];
__device__ float g_pool[BB * DD];

enum { MODE_PLAIN = 0, MODE_POS = 1, MODE_VT = 2, MODE_SCORES = 3, MODE_TAU = 4 };

// ---------------------------------------------------------------------------
// Generic tropical NT GEMM: 32x32 block tile, 128 threads, 2x4 per thread.
// A: [M, K] row-major (row stride K), B: [N, K] row-major (row stride K).
// ---------------------------------------------------------------------------
__global__ __launch_bounds__(128) void trop_gemm(
    const float* __restrict__ A, const float* __restrict__ B, float* __restrict__ C,
    int M, int N, int K, int ldc,
    int aBatch, int bBatch, int cBatch, int mode, const float* __restrict__ aux)
{
    __shared__ __align__(16) float As[32][36];  // [k][m]
    __shared__ __align__(16) float Bs[32][36];  // [k][n]

    const int t  = threadIdx.x;
    const int tx = t & 7;          // n-group (4 cols)
    const int ty = t >> 3;         // m-group (2 rows)
    const int bm = blockIdx.y << 5;
    const int bn = blockIdx.x << 5;

    const float* Ab = A + (long)blockIdx.z * aBatch;
    const float* Bb = B + (long)blockIdx.z * bBatch;

    float acc[2][4];
#pragma unroll
    for (int i = 0; i < 2; ++i)
#pragma unroll
        for (int j = 0; j < 4; ++j) acc[i][j] = NEG_INF;

    const int lr = ty;          // 0..15 (tile row this thread loads; +16 for 2nd)
    const int lk = tx << 2;     // 0,4,...,28

    for (int kk = 0; kk < K; kk += 32) {
#pragma unroll
        for (int hh = 0; hh < 2; ++hh) {
            int rowa = bm + lr + hh * 16;
            int ra = rowa < M ? rowa : M - 1;          // clamp (masked at store)
            float4 va = *(const float4*)(Ab + (long)ra * K + kk + lk);
            As[lk + 0][lr + hh * 16] = va.x;
            As[lk + 1][lr + hh * 16] = va.y;
            As[lk + 2][lr + hh * 16] = va.z;
            As[lk + 3][lr + hh * 16] = va.w;

            int rowb = bn + lr + hh * 16;
            int rb = rowb < N ? rowb : N - 1;          // clamp (pad-filled at store)
            float4 vb = *(const float4*)(Bb + (long)rb * K + kk + lk);
            Bs[lk + 0][lr + hh * 16] = vb.x;
            Bs[lk + 1][lr + hh * 16] = vb.y;
            Bs[lk + 2][lr + hh * 16] = vb.z;
            Bs[lk + 3][lr + hh * 16] = vb.w;
        }
        __syncthreads();
#pragma unroll
        for (int k = 0; k < 32; ++k) {
            float2 av = *(const float2*)&As[k][ty * 2];
            float4 bv = *(const float4*)&Bs[k][tx * 4];
            acc[0][0] = fmaxf(acc[0][0], av.x + bv.x);
            acc[0][1] = fmaxf(acc[0][1], av.x + bv.y);
            acc[0][2] = fmaxf(acc[0][2], av.x + bv.z);
            acc[0][3] = fmaxf(acc[0][3], av.x + bv.w);
            acc[1][0] = fmaxf(acc[1][0], av.y + bv.x);
            acc[1][1] = fmaxf(acc[1][1], av.y + bv.y);
            acc[1][2] = fmaxf(acc[1][2], av.y + bv.z);
            acc[1][3] = fmaxf(acc[1][3], av.y + bv.w);
        }
        __syncthreads();
    }

    float* Cb = C + (long)blockIdx.z * cBatch;
#pragma unroll
    for (int i = 0; i < 2; ++i) {
        int m = bm + ty * 2 + i;
        if (m >= M) continue;
#pragma unroll
        for (int j = 0; j < 4; ++j) {
            int n = bn + tx * 4 + j;
            float v = acc[i][j];
            if (mode == MODE_PLAIN) {
                Cb[(long)m * ldc + n] = v;
            } else if (mode == MODE_POS) {
                Cb[(long)m * ldc + n] = v + aux[(m % NPATCH) * DD + n];
            } else if (mode == MODE_VT) {
                int b = m / NPATCH, ii = m % NPATCH;
                C[((long)b * DD + n) * NPAD + ii] = v;   // transposed store
            } else if (mode == MODE_SCORES) {
                Cb[(long)m * ldc + n] = (n < N) ? v : NEG_INF;
            } else { // MODE_TAU
                Cb[(long)m * ldc + n] = fmaxf(v, aux[0]);
            }
        }
    }
}

// patchify: x(8,224,224) -> patches(8,196,256)
__global__ void patchify_k(const float* __restrict__ x)
{
    int bn = blockIdx.x;                 // 0..1567
    int b = bn / NPATCH, n = bn % NPATCH;
    int gr = n / 14, gc = n % 14;
    int j = threadIdx.x;                 // 0..255
    int pr = j >> 4, pc = j & 15;
    g_patches[(long)bn * PDIM + j] =
        x[((long)b * 224 + gr * 16 + pr) * 224 + gc * 16 + pc];
}

// xn = in - rowmax(in), rows of 128
__global__ void pnorm_k(const float* __restrict__ in, float* __restrict__ out)
{
    __shared__ float s[4];
    int r = blockIdx.x, t = threadIdx.x;
    float v = in[(long)r * DD + t];
    float m = v;
#pragma unroll
    for (int o = 16; o; o >>= 1) m = fmaxf(m, __shfl_xor_sync(0xffffffffu, m, o));
    if ((t & 31) == 0) s[t >> 5] = m;
    __syncthreads();
    m = fmaxf(fmaxf(s[0], s[1]), fmaxf(s[2], s[3]));
    out[(long)r * DD + t] = v - m;
}

// h = max(h, src - rowmax(src));  xn = h - rowmax(h)
__global__ void residual_k(const float* __restrict__ src, float* __restrict__ h,
                           float* __restrict__ xn)
{
    __shared__ float s[4];
    int r = blockIdx.x, t = threadIdx.x;
    long idx = (long)r * DD + t;
    float av = src[idx];
    float m = av;
#pragma unroll
    for (int o = 16; o; o >>= 1) m = fmaxf(m, __shfl_xor_sync(0xffffffffu, m, o));
    if ((t & 31) == 0) s[t >> 5] = m;
    __syncthreads();
    m = fmaxf(fmaxf(s[0], s[1]), fmaxf(s[2], s[3]));
    float hv = fmaxf(h[idx], av - m);
    h[idx] = hv;
    __syncthreads();
    float m2 = hv;
#pragma unroll
    for (int o = 16; o; o >>= 1) m2 = fmaxf(m2, __shfl_xor_sync(0xffffffffu, m2, o));
    if ((t & 31) == 0) s[t >> 5] = m2;
    __syncthreads();
    m2 = fmaxf(fmaxf(s[0], s[1]), fmaxf(s[2], s[3]));
    xn[idx] = hv - m2;
}

// scores row-normalize (max over valid 196 cols), rows of NPAD
__global__ void rownorm_scores_k()
{
    __shared__ float s[7];
    int r = blockIdx.x, t = threadIdx.x;    // 224 threads
    float* row = g_s + (long)r * NPAD;
    float v = row[t];
    float m = (t < NPATCH) ? v : NEG_INF;
#pragma unroll
    for (int o = 16; o; o >>= 1) m = fmaxf(m, __shfl_xor_sync(0xffffffffu, m, o));
    if ((t & 31) == 0) s[t >> 5] = m;
    __syncthreads();
    float mm = s[0];
#pragma unroll
    for (int i = 1; i < 7; ++i) mm = fmaxf(mm, s[i]);
    row[t] = v - mm;
}

// pooled[b,d] = max_n h[b,n,d]
__global__ void pool_k()
{
    int b = blockIdx.x, t = threadIdx.x;
    float acc = NEG_INF;
    const float* base = g_h + (long)b * NPATCH * DD + t;
    for (int n = 0; n < NPATCH; ++n) acc = fmaxf(acc, base[(long)n * DD]);
    g_pool[b * DD + t] = acc;
}

// logits[b,c] = max_d(pooled[b,d] + W[c,d]) * ls
__global__ void head_k(const float* __restrict__ W, const float* __restrict__ ls,
                       float* __restrict__ out)
{
    __shared__ float p[DD];
    int b = blockIdx.y, t = threadIdx.x;
    p[t] = g_pool[b * DD + t];
    __syncthreads();
    int c = blockIdx.x * 128 + t;
    if (c < NCLS) {
        float acc = NEG_INF;
        const float* w = W + (long)c * DD;
#pragma unroll 4
        for (int d = 0; d < DD; ++d) acc = fmaxf(acc, p[d] + w[d]);
        out[(long)b * NCLS + c] = acc * ls[0];
    }
}

// ---------------------------------------------------------------------------

extern "C" void kernel_launch(void* const* d_in, const int* in_sizes, int n_in,
                              void* d_out, int out_size)
{
    (void)in_sizes; (void)n_in; (void)out_size;
    const float* x       = (const float*)d_in[0];
    const float* embed_W = (const float*)d_in[1];
    const float* pos     = (const float*)d_in[2];
    const float* head_W  = (const float*)d_in[15];
    const float* lscale  = (const float*)d_in[16];
    float* out = (float*)d_out;

    float *patches, *h, *xn, *q, *k, *vT, *s, *a, *h1;
    cudaGetSymbolAddress((void**)&patches, g_patches);
    cudaGetSymbolAddress((void**)&h,  g_h);
    cudaGetSymbolAddress((void**)&xn, g_xn);
    cudaGetSymbolAddress((void**)&q,  g_q);
    cudaGetSymbolAddress((void**)&k,  g_k);
    cudaGetSymbolAddress((void**)&vT, g_vT);
    cudaGetSymbolAddress((void**)&s,  g_s);
    cudaGetSymbolAddress((void**)&a,  g_a);
    cudaGetSymbolAddress((void**)&h1, g_h1);

    patchify_k<<<MTOT, 256>>>(x);

    // embed: (1568x256) x (128x256)^T -> h, + pos
    trop_gemm<<<dim3(4, 49, 1), 128>>>(patches, embed_W, h,
        MTOT, DD, PDIM, DD, 0, 0, 0, MODE_POS, pos);
    pnorm_k<<<MTOT, 128>>>(h, xn);

    for (int l = 0; l < 2; ++l) {
        const float* qW  = (const float*)d_in[3 + 6 * l];
        const float* kW  = (const float*)d_in[4 + 6 * l];
        const float* vW  = (const float*)d_in[5 + 6 * l];
        const float* f1W = (const float*)d_in[6 + 6 * l];
        const float* f2W = (const float*)d_in[7 + 6 * l];
        const float* tau = (const float*)d_in[8 + 6 * l];

        trop_gemm<<<dim3(4, 49, 1), 128>>>(xn, qW, q,
            MTOT, DD, DD, DD, 0, 0, 0, MODE_PLAIN, nullptr);
        trop_gemm<<<dim3(4, 49, 1), 128>>>(xn, kW, k,
            MTOT, DD, DD, DD, 0, 0, 0, MODE_PLAIN, nullptr);
        trop_gemm<<<dim3(4, 49, 1), 128>>>(xn, vW, vT,
            MTOT, DD, DD, 0, 0, 0, 0, MODE_VT, nullptr);

        // scores: per-batch (196x128) x (196x128)^T -> (196 x NPAD)
        trop_gemm<<<dim3(7, 7, BB), 128>>>(q, k, s,
            NPATCH, NPATCH, DD, NPAD,
            NPATCH * DD, NPATCH * DD, NPATCH * NPAD, MODE_SCORES, nullptr);
        rownorm_scores_k<<<MTOT, NPAD>>>();

        // attn out: per-batch (196 x NPAD) x (128 x NPAD)^T -> (196x128)
        trop_gemm<<<dim3(4, 7, BB), 128>>>(s, vT, a,
            NPATCH, DD, NPAD, DD,
            NPATCH * NPAD, DD * NPAD, NPATCH * DD, MODE_PLAIN, nullptr);
        residual_k<<<MTOT, 128>>>(a, h, xn);

        // ff1: (1568x128) x (256x128)^T -> h1, tropical ReLU(tau)
        trop_gemm<<<dim3(8, 49, 1), 128>>>(xn, f1W, h1,
            MTOT, DFF, DD, DFF, 0, 0, 0, MODE_TAU, tau);
        // ff2: (1568x256) x (128x256)^T -> a
        trop_gemm<<<dim3(4, 49, 1), 128>>>(h1, f2W, a,
            MTOT, DD, DFF, DD, 0, 0, 0, MODE_PLAIN, nullptr);
        residual_k<<<MTOT, 128>>>(a, h, xn);
    }

    pool_k<<<BB, 128>>>();
    head_k<<<dim3(8, BB), 128>>>(head_W, lscale, out);
}

// round 3
// speedup vs baseline: 1.0004x; 1.0004x over previous
#include <cuda_runtime.h>

// ----------------------------------------------------------------------------
// Tropical (max-plus) ViT, fp32.  All matmuls: C[m,n] = max_k (A[m,k]+B[n,k]).
// Round 2: 64x32 tiles / 4x4 per thread / 128-thr blocks, qkv fusion,
// k-splitting for grid inflation, scores-norm algebraically eliminated,
// patchify fused into embed A-loader.
// ----------------------------------------------------------------------------

#define NEG_INF (-3.0e38f)
#define BB     8
#define NPATCH 196
#define DD     128
#define DFF    256
#define NPAD   224
#define MTOT   1568
#define NCLS   1000

__device__ float g_h   [MTOT * DD];
__device__ float g_xn  [MTOT * DD];
__device__ float g_q   [MTOT * DD];
__device__ float g_k   [MTOT * DD];
__device__ float g_vT  [BB * DD * NPAD];      // [b][d][j], j-pads stay 0
__device__ float g_s   [BB * NPATCH * NPAD];  // [b][i][j], j-pads = -inf
__device__ float g_a   [MTOT * DD];
__device__ float g_a2  [MTOT * DD];
__device__ float g_h1  [MTOT * DFF];
__device__ float g_pool[BB * DD];

enum { M_EMBED, M_QKV, M_SCORES, M_PLAIN, M_TAU };

// ---------------------------------------------------------------------------
// Tropical NT GEMM: 64x32 block tile, 128 threads, 4x4 per thread.
// A: [M,K] (row stride K), B: [N,K] (row stride K). Optional k-split halves
// (half 0 -> C0, half 1 -> C1), optional batching along blockIdx.z.
// ---------------------------------------------------------------------------
template<int MODE>
__global__ __launch_bounds__(128) void tg(
    const float* __restrict__ A, const float* __restrict__ B,
    const float* __restrict__ B2, const float* __restrict__ B3,
    float* __restrict__ C0, float* __restrict__ C1, float* __restrict__ C2,
    int M, int N, int K, int ldc,
    int aBatch, int bBatch, int cBatch,
    int nSplit, int kPerSplit, const float* __restrict__ aux)
{
    __shared__ __align__(16) float As[32][68];   // [k][m]
    __shared__ __align__(16) float Bs[32][36];   // [k][n]

    const int t  = threadIdx.x;
    const int tx = t & 7;          // n group (4 cols)
    const int ty = t >> 3;         // m group (4 rows)
    const int lk = tx << 2;        // loader k offset
    const int lr = ty;             // loader row offset
    const int bm = blockIdx.y << 6;
    const int bn = blockIdx.x << 5;

    int z = blockIdx.z, half = 0, batch = z;
    if (nSplit == 2) { half = z & 1; batch = z >> 1; }
    const int kBegin = half * kPerSplit;
    const int kEnd   = min(K, kBegin + kPerSplit);

    const float* Ab = A + (long)batch * aBatch;
    const float* Bb = B + (long)batch * bBatch;

    // Precompute per-thread row base pointers
    const float* arow[4];
#pragma unroll
    for (int h = 0; h < 4; ++h) {
        int ra = bm + lr + 16 * h; if (ra > M - 1) ra = M - 1;
        if (MODE == M_EMBED) {
            // fused patchify: row ra = (b, patch n); cols index (pr, pc)
            int b = ra / NPATCH, np = ra % NPATCH;
            int gr = np / 14, gc = np % 14;
            arow[h] = A + ((long)(b * 224 + gr * 16)) * 224 + gc * 16;
        } else {
            arow[h] = Ab + (long)ra * K;
        }
    }
    const float* brow[2];
#pragma unroll
    for (int h = 0; h < 2; ++h) {
        int rb = bn + lr + 16 * h; if (rb > N - 1) rb = N - 1;
        if (MODE == M_QKV) {
            const float* Bp = rb < 128 ? B : (rb < 256 ? B2 : B3);
            brow[h] = Bp + (long)(rb & 127) * K;
        } else {
            brow[h] = Bb + (long)rb * K;
        }
    }

    float acc[4][4];
#pragma unroll
    for (int i = 0; i < 4; ++i)
#pragma unroll
        for (int j = 0; j < 4; ++j) acc[i][j] = NEG_INF;

    for (int kk = kBegin; kk < kEnd; kk += 32) {
#pragma unroll
        for (int h = 0; h < 4; ++h) {
            float4 va;
            if (MODE == M_EMBED) {
                int j = kk + lk; int pr = j >> 4, pc = j & 15;
                va = *(const float4*)(arow[h] + pr * 224 + pc);
            } else {
                va = *(const float4*)(arow[h] + kk + lk);
            }
            As[lk + 0][lr + 16 * h] = va.x;
            As[lk + 1][lr + 16 * h] = va.y;
            As[lk + 2][lr + 16 * h] = va.z;
            As[lk + 3][lr + 16 * h] = va.w;
        }
#pragma unroll
        for (int h = 0; h < 2; ++h) {
            float4 vb = *(const float4*)(brow[h] + kk + lk);
            Bs[lk + 0][lr + 16 * h] = vb.x;
            Bs[lk + 1][lr + 16 * h] = vb.y;
            Bs[lk + 2][lr + 16 * h] = vb.z;
            Bs[lk + 3][lr + 16 * h] = vb.w;
        }
        __syncthreads();
#pragma unroll
        for (int k = 0; k < 32; ++k) {
            float4 av = *(const float4*)&As[k][ty * 4];
            float4 bv = *(const float4*)&Bs[k][tx * 4];
            acc[0][0] = fmaxf(acc[0][0], av.x + bv.x);
            acc[0][1] = fmaxf(acc[0][1], av.x + bv.y);
            acc[0][2] = fmaxf(acc[0][2], av.x + bv.z);
            acc[0][3] = fmaxf(acc[0][3], av.x + bv.w);
            acc[1][0] = fmaxf(acc[1][0], av.y + bv.x);
            acc[1][1] = fmaxf(acc[1][1], av.y + bv.y);
            acc[1][2] = fmaxf(acc[1][2], av.y + bv.z);
            acc[1][3] = fmaxf(acc[1][3], av.y + bv.w);
            acc[2][0] = fmaxf(acc[2][0], av.z + bv.x);
            acc[2][1] = fmaxf(acc[2][1], av.z + bv.y);
            acc[2][2] = fmaxf(acc[2][2], av.z + bv.z);
            acc[2][3] = fmaxf(acc[2][3], av.z + bv.w);
            acc[3][0] = fmaxf(acc[3][0], av.w + bv.x);
            acc[3][1] = fmaxf(acc[3][1], av.w + bv.y);
            acc[3][2] = fmaxf(acc[3][2], av.w + bv.z);
            acc[3][3] = fmaxf(acc[3][3], av.w + bv.w);
        }
        __syncthreads();
    }

    float* Ch = half ? C1 : C0;
#pragma unroll
    for (int i = 0; i < 4; ++i) {
        int m = bm + ty * 4 + i;
        if (m >= M) continue;
#pragma unroll
        for (int j = 0; j < 4; ++j) {
            int n = bn + tx * 4 + j;
            float v = acc[i][j];
            if (MODE == M_EMBED) {
                Ch[(long)m * ldc + n] = v + aux[(m % NPATCH) * DD + n];
            } else if (MODE == M_QKV) {
                if (n < DD)            C0[(long)m * DD + n] = v;
                else if (n < 2 * DD)   C1[(long)m * DD + (n - DD)] = v;
                else {
                    int b = m / NPATCH, ii = m % NPATCH;
                    C2[((long)b * DD + (n - 2 * DD)) * NPAD + ii] = v;
                }
            } else if (MODE == M_SCORES) {
                (C0 + (long)batch * cBatch)[(long)m * ldc + n] =
                    (n < N) ? v : NEG_INF;
            } else if (MODE == M_TAU) {
                C0[(long)m * ldc + n] = fmaxf(v, aux[0]);
            } else {  // M_PLAIN
                (Ch + (long)batch * cBatch)[(long)m * ldc + n] = v;
            }
        }
    }
}

// h = max(a0,a1);  xn = h - rowmax(h)    (embed + pnorm combine)
__global__ void pnorm2_k(const float* __restrict__ a0, const float* __restrict__ a1,
                         float* __restrict__ h, float* __restrict__ xn)
{
    __shared__ float s[4];
    int r = blockIdx.x, t = threadIdx.x;
    long idx = (long)r * DD + t;
    float v = fmaxf(a0[idx], a1[idx]);
    float m = v;
#pragma unroll
    for (int o = 16; o; o >>= 1) m = fmaxf(m, __shfl_xor_sync(0xffffffffu, m, o));
    if ((t & 31) == 0) s[t >> 5] = m;
    __syncthreads();
    m = fmaxf(fmaxf(s[0], s[1]), fmaxf(s[2], s[3]));
    h[idx] = v;
    xn[idx] = v - m;
}

// src = max(s0,s1); h = max(h, src - rowmax(src)); xn = h - rowmax(h)
__global__ void residual2_k(const float* __restrict__ s0, const float* __restrict__ s1,
                            float* __restrict__ h, float* __restrict__ xn)
{
    __shared__ float s[4];
    int r = blockIdx.x, t = threadIdx.x;
    long idx = (long)r * DD + t;
    float av = fmaxf(s0[idx], s1[idx]);
    float m = av;
#pragma unroll
    for (int o = 16; o; o >>= 1) m = fmaxf(m, __shfl_xor_sync(0xffffffffu, m, o));
    if ((t & 31) == 0) s[t >> 5] = m;
    __syncthreads();
    m = fmaxf(fmaxf(s[0], s[1]), fmaxf(s[2], s[3]));
    float hv = fmaxf(h[idx], av - m);
    h[idx] = hv;
    __syncthreads();
    float m2 = hv;
#pragma unroll
    for (int o = 16; o; o >>= 1) m2 = fmaxf(m2, __shfl_xor_sync(0xffffffffu, m2, o));
    if ((t & 31) == 0) s[t >> 5] = m2;
    __syncthreads();
    m2 = fmaxf(fmaxf(s[0], s[1]), fmaxf(s[2], s[3]));
    xn[idx] = hv - m2;
}

// pooled[b,d] = max_n h[b,n,d]
__global__ void pool_k()
{
    int b = blockIdx.x, t = threadIdx.x;
    float acc = NEG_INF;
    const float* base = g_h + (long)b * NPATCH * DD + t;
#pragma unroll 4
    for (int n = 0; n < NPATCH; ++n) acc = fmaxf(acc, base[(long)n * DD]);
    g_pool[b * DD + t] = acc;
}

// logits[b,c] = max_d(pooled[b,d] + W[c,d]) * ls
__global__ void head_k(const float* __restrict__ W, const float* __restrict__ ls,
                       float* __restrict__ out)
{
    __shared__ float p[DD];
    int b = blockIdx.y, t = threadIdx.x;
    p[t] = g_pool[b * DD + t];
    __syncthreads();
    int c = blockIdx.x * 128 + t;
    if (c < NCLS) {
        float acc = NEG_INF;
        const float* w = W + (long)c * DD;
#pragma unroll 4
        for (int d = 0; d < DD; ++d) acc = fmaxf(acc, p[d] + w[d]);
        out[(long)b * NCLS + c] = acc * ls[0];
    }
}

// ---------------------------------------------------------------------------

extern "C" void kernel_launch(void* const* d_in, const int* in_sizes, int n_in,
                              void* d_out, int out_size)
{
    (void)in_sizes; (void)n_in; (void)out_size;
    const float* x       = (const float*)d_in[0];
    const float* embed_W = (const float*)d_in[1];
    const float* pos     = (const float*)d_in[2];
    const float* head_W  = (const float*)d_in[15];
    const float* lscale  = (const float*)d_in[16];
    float* out = (float*)d_out;

    float *h, *xn, *q, *k, *vT, *s, *a, *a2, *h1;
    cudaGetSymbolAddress((void**)&h,  g_h);
    cudaGetSymbolAddress((void**)&xn, g_xn);
    cudaGetSymbolAddress((void**)&q,  g_q);
    cudaGetSymbolAddress((void**)&k,  g_k);
    cudaGetSymbolAddress((void**)&vT, g_vT);
    cudaGetSymbolAddress((void**)&s,  g_s);
    cudaGetSymbolAddress((void**)&a,  g_a);
    cudaGetSymbolAddress((void**)&a2, g_a2);
    cudaGetSymbolAddress((void**)&h1, g_h1);

    // embed (patchify fused into A-loader), K=256 split in 2 -> h / a
    tg<M_EMBED><<<dim3(4, 25, 2), 128>>>(x, embed_W, 0, 0, h, a, 0,
        MTOT, DD, 256, DD, 0, 0, 0, 2, 128, pos);
    pnorm2_k<<<MTOT, 128>>>(h, a, h, xn);

    for (int l = 0; l < 2; ++l) {
        const float* qW  = (const float*)d_in[3 + 6 * l];
        const float* kW  = (const float*)d_in[4 + 6 * l];
        const float* vW  = (const float*)d_in[5 + 6 * l];
        const float* f1W = (const float*)d_in[6 + 6 * l];
        const float* f2W = (const float*)d_in[7 + 6 * l];
        const float* tau = (const float*)d_in[8 + 6 * l];

        // fused q/k/v: N=384 (B selected per 128-row band)
        tg<M_QKV><<<dim3(12, 25, 1), 128>>>(xn, qW, kW, vW, q, k, vT,
            MTOT, 384, DD, 0, 0, 0, 0, 1, DD, 0);

        // scores per batch: (196x128) x (196x128)^T -> (196 x 224)
        tg<M_SCORES><<<dim3(7, 4, 8), 128>>>(q, k, 0, 0, s, 0, 0,
            NPATCH, NPATCH, DD, NPAD,
            NPATCH * DD, NPATCH * DD, NPATCH * NPAD, 1, DD, 0);

        // attn out per batch, K=224 split (128+96) -> a / a2
        // (scores row-normalization cancels inside the following pnorm)
        tg<M_PLAIN><<<dim3(4, 4, 16), 128>>>(s, vT, 0, 0, a, a2, 0,
            NPATCH, DD, NPAD, DD,
            NPATCH * NPAD, DD * NPAD, NPATCH * DD, 2, 128, 0);
        residual2_k<<<MTOT, 128>>>(a, a2, h, xn);

        // ff1: N=256, tropical ReLU(tau)
        tg<M_TAU><<<dim3(8, 25, 1), 128>>>(xn, f1W, 0, 0, h1, 0, 0,
            MTOT, DFF, DD, DFF, 0, 0, 0, 1, DD, tau);

        // ff2: K=256 split in 2 -> a / a2
        tg<M_PLAIN><<<dim3(4, 25, 2), 128>>>(h1, f2W, 0, 0, a, a2, 0,
            MTOT, DD, DFF, DD, 0, 0, 0, 2, 128, 0);
        residual2_k<<<MTOT, 128>>>(a, a2, h, xn);
    }

    pool_k<<<BB, 128>>>();
    head_k<<<dim3(8, BB), 128>>>(head_W, lscale, out);
}

// round 4
// speedup vs baseline: 1.2575x; 1.2570x over previous
#include <cuda_runtime.h>

// ----------------------------------------------------------------------------
// Tropical (max-plus) ViT, fp32.  All matmuls: C[m,n] = max_k (A[m,k]+B[n,k]).
// Round 3: occupancy-first. 32x32 tiles / 128 threads / 2x4 per thread,
// k-split2 on big-K GEMMs (combine folded into follower kernels).
// ----------------------------------------------------------------------------

#define NEG_INF (-3.0e38f)
#define BB     8
#define NPATCH 196
#define DD     128
#define DFF    256
#define NPAD   224
#define MTOT   1568
#define NCLS   1000

__device__ float g_h   [MTOT * DD];
__device__ float g_xn  [MTOT * DD];
__device__ float g_q   [MTOT * DD];
__device__ float g_k   [MTOT * DD];
__device__ float g_vT  [BB * DD * NPAD];      // [b][d][j], j-pads stay 0
__device__ float g_s   [BB * NPATCH * NPAD];  // [b][i][j], j-pads = -inf
__device__ float g_a   [MTOT * DD];
__device__ float g_a2  [MTOT * DD];
__device__ float g_h1  [MTOT * DFF];
__device__ float g_pool[BB * DD];

enum { M_EMBED, M_QKV, M_SCORES, M_PLAIN, M_TAU };

// ---------------------------------------------------------------------------
// Tropical NT GEMM: 32x32 block tile, 128 threads, 2x4 per thread.
// A: [M,K] row stride K; B: [N,K] row stride K.
// Optional k-split halves (half0 -> C0, half1 -> C1) decoded from blockIdx.z.
// ---------------------------------------------------------------------------
template<int MODE>
__global__ __launch_bounds__(128) void tg(
    const float* __restrict__ A, const float* __restrict__ B,
    const float* __restrict__ B2, const float* __restrict__ B3,
    float* __restrict__ C0, float* __restrict__ C1, float* __restrict__ C2,
    int M, int N, int K, int ldc,
    int aBatch, int bBatch, int cBatch,
    int nSplit, int kPerSplit, const float* __restrict__ aux)
{
    __shared__ __align__(16) float As[32][34];   // [k][m], stride 34 (8B align)
    __shared__ __align__(16) float Bs[32][36];   // [k][n], stride 36 (16B align)

    const int t  = threadIdx.x;
    const int tx = t & 7;          // n group (4 cols)
    const int ty = t >> 3;         // m group (2 rows)
    const int lk = tx << 2;        // loader k offset (0,4,...,28)
    const int lr = ty;             // loader row (0..15; +16 second row)
    const int bm = blockIdx.y << 5;
    const int bn = blockIdx.x << 5;

    int z = blockIdx.z, half = 0, batch = z;
    if (nSplit == 2) { half = z & 1; batch = z >> 1; }
    const int kBegin = half * kPerSplit;
    const int kEnd   = min(K, kBegin + kPerSplit);

    const float* Ab = A + (long)batch * aBatch;
    const float* Bb = B + (long)batch * bBatch;

    const float* arow[2];
#pragma unroll
    for (int h = 0; h < 2; ++h) {
        int ra = bm + lr + 16 * h; if (ra > M - 1) ra = M - 1;
        if (MODE == M_EMBED) {
            int b = ra / NPATCH, np = ra % NPATCH;
            int gr = np / 14, gc = np % 14;
            arow[h] = A + ((long)(b * 224 + gr * 16)) * 224 + gc * 16;
        } else {
            arow[h] = Ab + (long)ra * K;
        }
    }
    const float* brow[2];
#pragma unroll
    for (int h = 0; h < 2; ++h) {
        int rb = bn + lr + 16 * h; if (rb > N - 1) rb = N - 1;
        if (MODE == M_QKV) {
            const float* Bp = rb < 128 ? B : (rb < 256 ? B2 : B3);
            brow[h] = Bp + (long)(rb & 127) * K;
        } else {
            brow[h] = Bb + (long)rb * K;
        }
    }

    float acc[2][4];
#pragma unroll
    for (int i = 0; i < 2; ++i)
#pragma unroll
        for (int j = 0; j < 4; ++j) acc[i][j] = NEG_INF;

    for (int kk = kBegin; kk < kEnd; kk += 32) {
#pragma unroll
        for (int h = 0; h < 2; ++h) {
            float4 va;
            if (MODE == M_EMBED) {
                int j = kk + lk; int pr = j >> 4, pc = j & 15;
                va = *(const float4*)(arow[h] + pr * 224 + pc);
            } else {
                va = *(const float4*)(arow[h] + kk + lk);
            }
            As[lk + 0][lr + 16 * h] = va.x;
            As[lk + 1][lr + 16 * h] = va.y;
            As[lk + 2][lr + 16 * h] = va.z;
            As[lk + 3][lr + 16 * h] = va.w;

            float4 vb = *(const float4*)(brow[h] + kk + lk);
            Bs[lk + 0][lr + 16 * h] = vb.x;
            Bs[lk + 1][lr + 16 * h] = vb.y;
            Bs[lk + 2][lr + 16 * h] = vb.z;
            Bs[lk + 3][lr + 16 * h] = vb.w;
        }
        __syncthreads();
#pragma unroll
        for (int k = 0; k < 32; ++k) {
            float2 av = *(const float2*)&As[k][ty * 2];
            float4 bv = *(const float4*)&Bs[k][tx * 4];
            acc[0][0] = fmaxf(acc[0][0], av.x + bv.x);
            acc[0][1] = fmaxf(acc[0][1], av.x + bv.y);
            acc[0][2] = fmaxf(acc[0][2], av.x + bv.z);
            acc[0][3] = fmaxf(acc[0][3], av.x + bv.w);
            acc[1][0] = fmaxf(acc[1][0], av.y + bv.x);
            acc[1][1] = fmaxf(acc[1][1], av.y + bv.y);
            acc[1][2] = fmaxf(acc[1][2], av.y + bv.z);
            acc[1][3] = fmaxf(acc[1][3], av.y + bv.w);
        }
        __syncthreads();
    }

    float* Ch = half ? C1 : C0;
#pragma unroll
    for (int i = 0; i < 2; ++i) {
        int m = bm + ty * 2 + i;
        if (m >= M) continue;
#pragma unroll
        for (int j = 0; j < 4; ++j) {
            int n = bn + tx * 4 + j;
            float v = acc[i][j];
            if (MODE == M_EMBED) {
                Ch[(long)m * ldc + n] = v + aux[(m % NPATCH) * DD + n];
            } else if (MODE == M_QKV) {
                if (n < DD)            C0[(long)m * DD + n] = v;
                else if (n < 2 * DD)   C1[(long)m * DD + (n - DD)] = v;
                else {
                    int b = m / NPATCH, ii = m % NPATCH;
                    C2[((long)b * DD + (n - 2 * DD)) * NPAD + ii] = v;
                }
            } else if (MODE == M_SCORES) {
                (C0 + (long)batch * cBatch)[(long)m * ldc + n] =
                    (n < N) ? v : NEG_INF;
            } else if (MODE == M_TAU) {
                C0[(long)m * ldc + n] = fmaxf(v, aux[0]);
            } else {  // M_PLAIN
                (Ch + (long)batch * cBatch)[(long)m * ldc + n] = v;
            }
        }
    }
}

// h = max(a0,a1);  xn = h - rowmax(h)
__global__ void pnorm2_k(const float* __restrict__ a0, const float* __restrict__ a1,
                         float* __restrict__ h, float* __restrict__ xn)
{
    __shared__ float s[4];
    int r = blockIdx.x, t = threadIdx.x;
    long idx = (long)r * DD + t;
    float v = fmaxf(a0[idx], a1[idx]);
    float m = v;
#pragma unroll
    for (int o = 16; o; o >>= 1) m = fmaxf(m, __shfl_xor_sync(0xffffffffu, m, o));
    if ((t & 31) == 0) s[t >> 5] = m;
    __syncthreads();
    m = fmaxf(fmaxf(s[0], s[1]), fmaxf(s[2], s[3]));
    h[idx] = v;
    xn[idx] = v - m;
}

// src = max(s0,s1); h = max(h, src - rowmax(src)); xn = h - rowmax(h)
__global__ void residual2_k(const float* __restrict__ s0, const float* __restrict__ s1,
                            float* __restrict__ h, float* __restrict__ xn)
{
    __shared__ float s[4];
    int r = blockIdx.x, t = threadIdx.x;
    long idx = (long)r * DD + t;
    float av = fmaxf(s0[idx], s1[idx]);
    float m = av;
#pragma unroll
    for (int o = 16; o; o >>= 1) m = fmaxf(m, __shfl_xor_sync(0xffffffffu, m, o));
    if ((t & 31) == 0) s[t >> 5] = m;
    __syncthreads();
    m = fmaxf(fmaxf(s[0], s[1]), fmaxf(s[2], s[3]));
    float hv = fmaxf(h[idx], av - m);
    h[idx] = hv;
    __syncthreads();
    float m2 = hv;
#pragma unroll
    for (int o = 16; o; o >>= 1) m2 = fmaxf(m2, __shfl_xor_sync(0xffffffffu, m2, o));
    if ((t & 31) == 0) s[t >> 5] = m2;
    __syncthreads();
    m2 = fmaxf(fmaxf(s[0], s[1]), fmaxf(s[2], s[3]));
    xn[idx] = hv - m2;
}

__global__ void pool_k()
{
    int b = blockIdx.x, t = threadIdx.x;
    float acc = NEG_INF;
    const float* base = g_h + (long)b * NPATCH * DD + t;
#pragma unroll 4
    for (int n = 0; n < NPATCH; ++n) acc = fmaxf(acc, base[(long)n * DD]);
    g_pool[b * DD + t] = acc;
}

__global__ void head_k(const float* __restrict__ W, const float* __restrict__ ls,
                       float* __restrict__ out)
{
    __shared__ float p[DD];
    int b = blockIdx.y, t = threadIdx.x;
    p[t] = g_pool[b * DD + t];
    __syncthreads();
    int c = blockIdx.x * 128 + t;
    if (c < NCLS) {
        float acc = NEG_INF;
        const float* w = W + (long)c * DD;
#pragma unroll 4
        for (int d = 0; d < DD; ++d) acc = fmaxf(acc, p[d] + w[d]);
        out[(long)b * NCLS + c] = acc * ls[0];
    }
}

// ---------------------------------------------------------------------------

extern "C" void kernel_launch(void* const* d_in, const int* in_sizes, int n_in,
                              void* d_out, int out_size)
{
    (void)in_sizes; (void)n_in; (void)out_size;
    const float* x       = (const float*)d_in[0];
    const float* embed_W = (const float*)d_in[1];
    const float* pos     = (const float*)d_in[2];
    const float* head_W  = (const float*)d_in[15];
    const float* lscale  = (const float*)d_in[16];
    float* out = (float*)d_out;

    float *h, *xn, *q, *k, *vT, *s, *a, *a2, *h1;
    cudaGetSymbolAddress((void**)&h,  g_h);
    cudaGetSymbolAddress((void**)&xn, g_xn);
    cudaGetSymbolAddress((void**)&q,  g_q);
    cudaGetSymbolAddress((void**)&k,  g_k);
    cudaGetSymbolAddress((void**)&vT, g_vT);
    cudaGetSymbolAddress((void**)&s,  g_s);
    cudaGetSymbolAddress((void**)&a,  g_a);
    cudaGetSymbolAddress((void**)&a2, g_a2);
    cudaGetSymbolAddress((void**)&h1, g_h1);

    // embed (patchify fused), K=256 split2 -> h / a ; combine in pnorm2
    tg<M_EMBED><<<dim3(4, 49, 2), 128>>>(x, embed_W, 0, 0, h, a, 0,
        MTOT, DD, 256, DD, 0, 0, 0, 2, 128, pos);
    pnorm2_k<<<MTOT, 128>>>(h, a, h, xn);

    for (int l = 0; l < 2; ++l) {
        const float* qW  = (const float*)d_in[3 + 6 * l];
        const float* kW  = (const float*)d_in[4 + 6 * l];
        const float* vW  = (const float*)d_in[5 + 6 * l];
        const float* f1W = (const float*)d_in[6 + 6 * l];
        const float* f2W = (const float*)d_in[7 + 6 * l];
        const float* tau = (const float*)d_in[8 + 6 * l];

        // fused q/k/v: N=384
        tg<M_QKV><<<dim3(12, 49, 1), 128>>>(xn, qW, kW, vW, q, k, vT,
            MTOT, 384, DD, 0, 0, 0, 0, 1, DD, 0);

        // scores per batch: (196x128) x (196x128)^T -> (196 x 224)
        tg<M_SCORES><<<dim3(7, 7, 8), 128>>>(q, k, 0, 0, s, 0, 0,
            NPATCH, NPATCH, DD, NPAD,
            NPATCH * DD, NPATCH * DD, NPATCH * NPAD, 1, DD, 0);

        // attn out per batch, K=224 split (128+96) -> a / a2 ; combine in residual2
        tg<M_PLAIN><<<dim3(4, 7, 16), 128>>>(s, vT, 0, 0, a, a2, 0,
            NPATCH, DD, NPAD, DD,
            NPATCH * NPAD, DD * NPAD, NPATCH * DD, 2, 128, 0);
        residual2_k<<<MTOT, 128>>>(a, a2, h, xn);

        // ff1: N=256, tropical ReLU(tau)
        tg<M_TAU><<<dim3(8, 49, 1), 128>>>(xn, f1W, 0, 0, h1, 0, 0,
            MTOT, DFF, DD, DFF, 0, 0, 0, 1, DD, tau);

        // ff2: K=256 split2 -> a / a2 ; combine in residual2
        tg<M_PLAIN><<<dim3(4, 49, 2), 128>>>(h1, f2W, 0, 0, a, a2, 0,
            MTOT, DD, DFF, DD, 0, 0, 0, 2, 128, 0);
        residual2_k<<<MTOT, 128>>>(a, a2, h, xn);
    }

    pool_k<<<BB, 128>>>();
    head_k<<<dim3(8, BB), 128>>>(head_W, lscale, out);
}